// round 5
// baseline (speedup 1.0000x reference)
#include <cuda_runtime.h>
#include <cuda_fp16.h>
#include <math.h>
#include <stdint.h>

#define CBATCH   4
#define CSEQ     2048
#define CDMODEL  1024
#define CDMAMBA  2048
#define CDSTATE  16
#define CNHEADS  32
#define CMROWS   (CBATCH * CSEQ)          // 8192
#define CNCHUNK  32
#define CLCHUNK  (CSEQ / CNCHUNK)         // 64
#define CHEADDIM (CDMAMBA / CNHEADS)      // 64

typedef unsigned short ushort_t;

// ---------------- scratch (static device arrays; no runtime allocation) ----------------
__device__ float g_xssm[CMROWS * CDMAMBA];
__device__ float g_dt  [CMROWS * CDMAMBA];
__device__ float g_Bn  [CMROWS * CDSTATE];
__device__ float g_Cn  [CMROWS * CDSTATE];
__device__ float g_hloc [CBATCH * CNCHUNK * CDSTATE * CDMAMBA];
__device__ float g_hinit[CBATCH * CNCHUNK * CDSTATE * CDMAMBA];
__device__ float g_S    [CBATCH * CNCHUNK * CDMAMBA];

// fp16 split operands: A-side hi+lo, W-side hi only
__device__ ushort_t g_xn_h[CMROWS * CDMODEL];
__device__ ushort_t g_xn_l[CMROWS * CDMODEL];
__device__ ushort_t g_w1_h[CDMAMBA * CDMODEL];
__device__ ushort_t g_w2_h[CDMAMBA * CDMODEL];
__device__ ushort_t g_w3_h[CDMAMBA * CDMAMBA];
__device__ ushort_t g_y_h[CMROWS * CDMAMBA];
__device__ ushort_t g_y_l[CMROWS * CDMAMBA];

// ---------------- PTX helpers (baseline sm_80-level features only) ----------------
__device__ __forceinline__ uint32_t smem_u32(const void* p) {
    uint32_t a;
    asm("{ .reg .u64 t; cvta.to.shared.u64 t, %1; cvt.u32.u64 %0, t; }" : "=r"(a) : "l"(p));
    return a;
}

#define CP_ASYNC16(dst, src) \
    asm volatile("cp.async.cg.shared.global [%0], [%1], 16;" :: "r"(dst), "l"(src))
#define CP_COMMIT() asm volatile("cp.async.commit_group;" ::: "memory")
#define CP_WAIT0() asm volatile("cp.async.wait_group 0;" ::: "memory")
#define CP_WAIT1() asm volatile("cp.async.wait_group 1;" ::: "memory")

#define LDSM4(r, addr) \
    asm volatile("ldmatrix.sync.aligned.m8n8.x4.shared.b16 {%0,%1,%2,%3}, [%4];" \
        : "=r"((r)[0]), "=r"((r)[1]), "=r"((r)[2]), "=r"((r)[3]) : "r"(addr))

#define MMA_F16(d, a, b0, b1) \
    asm volatile("mma.sync.aligned.m16n8k16.row.col.f32.f16.f16.f32 " \
        "{%0,%1,%2,%3}, {%4,%5,%6,%7}, {%8,%9}, {%0,%1,%2,%3};" \
        : "+f"((d)[0]), "+f"((d)[1]), "+f"((d)[2]), "+f"((d)[3]) \
        : "r"((a)[0]), "r"((a)[1]), "r"((a)[2]), "r"((a)[3]), "r"(b0), "r"(b1))

__device__ __forceinline__ uint32_t swz(uint32_t off) {   // SW128 xor swizzle
    return off ^ ((off >> 3) & 0x70);
}

// ---------------- fp16 split conversion ----------------
__device__ __forceinline__ void split1(float v, ushort_t& h, ushort_t& l) {
    __half hh = __float2half(v);
    h = __half_as_ushort(hh);
    l = __half_as_ushort(__float2half(v - __half2float(hh)));
}

__global__ __launch_bounds__(256) void conv_split(const float* __restrict__ in,
                                                  ushort_t* __restrict__ hi,
                                                  ushort_t* __restrict__ lo,
                                                  int n4) {
    int i = blockIdx.x * 256 + threadIdx.x;
    if (i >= n4) return;
    float4 v = reinterpret_cast<const float4*>(in)[i];
    ushort4 h, l;
    split1(v.x, h.x, l.x);
    split1(v.y, h.y, l.y);
    split1(v.z, h.z, l.z);
    split1(v.w, h.w, l.w);
    reinterpret_cast<ushort4*>(hi)[i] = h;
    reinterpret_cast<ushort4*>(lo)[i] = l;
}

__global__ __launch_bounds__(256) void conv_h(const float* __restrict__ in,
                                              ushort_t* __restrict__ hi, int n4) {
    int i = blockIdx.x * 256 + threadIdx.x;
    if (i >= n4) return;
    float4 v = reinterpret_cast<const float4*>(in)[i];
    ushort4 h;
    h.x = __half_as_ushort(__float2half(v.x));
    h.y = __half_as_ushort(__float2half(v.y));
    h.z = __half_as_ushort(__float2half(v.z));
    h.w = __half_as_ushort(__float2half(v.w));
    reinterpret_cast<ushort4*>(hi)[i] = h;
}

__device__ __forceinline__ float dt_transform(float v, float b) {
    v += b;
    v = fminf(fmaxf(v, -10.0f), 5.0f);
    v = log1pf(expf(v));
    return fminf(fmaxf(v, 1e-4f), 0.1f);
}

// ---------------- HMMA fp16x2 GEMM, 3-stage single-sync pipeline ----------------
// C[m,n] = sum_k A[m,k]*W[n,k] ~= (Ah+Al)[m,:]*Wh[n,:]
// CTA tile 128x128, BK=64, 512 threads (4x4 warps, 32x32 warp tiles).
// 3 stages x 48KB = 144KB smem, 1 CTA/SM, ONE __syncthreads per K-chunk.
#define TILE_B   16384
#define STAGE_B  49152
#define NSTAGE   3
#define SM_TOTAL (NSTAGE * STAGE_B)   // 147456

__device__ __forceinline__ void stage_load(
    const ushort_t* __restrict__ Ah, const ushort_t* __restrict__ Al,
    const ushort_t* __restrict__ Wh,
    uint32_t sbase, int m0, int n0, int kc, int K, int tid) {
#pragma unroll
    for (int tile = 0; tile < 3; tile++) {
        const ushort_t* g = (tile == 0) ? Ah : (tile == 1) ? Al : Wh;
        int row0 = (tile < 2) ? m0 : n0;
#pragma unroll
        for (int j = 0; j < 2; j++) {
            int idx = tid + j * 512;           // 0..1023
            int row = idx >> 3, seg = idx & 7;
            const ushort_t* src = g + (size_t)(row0 + row) * K + kc + seg * 8;
            uint32_t dst = sbase + tile * TILE_B + swz((uint32_t)(row * 128 + seg * 16));
            CP_ASYNC16(dst, src);
        }
    }
}

__device__ __forceinline__ void stage_compute(uint32_t sbase, int wm, int wn,
                                              int lane, float acc[2][4][4]) {
    const uint32_t aAh = sbase;
    const uint32_t aAl = sbase + TILE_B;
    const uint32_t aWh = sbase + 2 * TILE_B;
    const int arow = wm + (lane & 15);
    const int akb  = (lane >> 4) * 16;
    const int brow = wn + ((lane >> 4) << 3) + (lane & 7);
    const int bkb  = ((lane >> 3) & 1) * 16;

#pragma unroll
    for (int ks = 0; ks < 4; ks++) {
        const int kb = ks * 32;
        uint32_t ah[2][4], al[2][4];
#pragma unroll
        for (int mi = 0; mi < 2; mi++) {
            uint32_t off = swz((uint32_t)((arow + mi * 16) * 128 + akb + kb));
            LDSM4(ah[mi], aAh + off);
            LDSM4(al[mi], aAl + off);
        }
        uint32_t bh[2][4];
#pragma unroll
        for (int ni = 0; ni < 2; ni++) {
            uint32_t off = swz((uint32_t)((brow + ni * 16) * 128 + bkb + kb));
            LDSM4(bh[ni], aWh + off);
        }
#pragma unroll
        for (int mi = 0; mi < 2; mi++) {
#pragma unroll
            for (int ni = 0; ni < 2; ni++) {
                MMA_F16(acc[mi][2 * ni + 0], ah[mi], bh[ni][0], bh[ni][1]);
                MMA_F16(acc[mi][2 * ni + 0], al[mi], bh[ni][0], bh[ni][1]);
                MMA_F16(acc[mi][2 * ni + 1], ah[mi], bh[ni][2], bh[ni][3]);
                MMA_F16(acc[mi][2 * ni + 1], al[mi], bh[ni][2], bh[ni][3]);
            }
        }
    }
}

// Blocks with blockIdx.x < n1blk compute C1 = A*W1^T (identity epilogue).
// Blocks with blockIdx.x >= n1blk compute C2 = dt_transform(A*W2^T + bias).
__global__ __launch_bounds__(512, 1) void gemm_mma(
    const ushort_t* __restrict__ Ah, const ushort_t* __restrict__ Al,
    const ushort_t* __restrict__ W1, const ushort_t* __restrict__ W2,
    const float* __restrict__ bias, float* __restrict__ C1, float* __restrict__ C2,
    int n1blk, int N, int K) {
    extern __shared__ __align__(1024) char smem[];
    const uint32_t sb = smem_u32(smem);
    const int tid = threadIdx.x, lane = tid & 31, w = tid >> 5;
    const int m0 = blockIdx.y * 128;
    const bool second = ((int)blockIdx.x >= n1blk);
    const int n0 = (second ? (int)blockIdx.x - n1blk : (int)blockIdx.x) * 128;
    const ushort_t* Wh = second ? W2 : W1;
    float* C = second ? C2 : C1;
    const int wm = (w & 3) * 32, wn = (w >> 2) * 32;
    const int NC = K >> 6;

    float acc[2][4][4];
#pragma unroll
    for (int i = 0; i < 2; i++)
#pragma unroll
        for (int j = 0; j < 4; j++)
#pragma unroll
            for (int q = 0; q < 4; q++) acc[i][j][q] = 0.0f;

    stage_load(Ah, Al, Wh, sb + 0 * STAGE_B, m0, n0, 0, K, tid);  CP_COMMIT();
    stage_load(Ah, Al, Wh, sb + 1 * STAGE_B, m0, n0, 64, K, tid); CP_COMMIT();

    int s = 0, sload = 2;
    for (int c = 0; c < NC; c++) {
        if (c + 1 < NC) { CP_WAIT1(); } else { CP_WAIT0(); }
        __syncthreads();
        if (c + 2 < NC) {
            stage_load(Ah, Al, Wh, sb + sload * STAGE_B, m0, n0, (c + 2) * 64, K, tid);
            CP_COMMIT();
        }
        stage_compute(sb + s * STAGE_B, wm, wn, lane, acc);
        s = (s == 2) ? 0 : s + 1;
        sload = (sload == 2) ? 0 : sload + 1;
    }

    // epilogue
    const int gm = m0 + wm, gn = n0 + wn;
    const int r = lane >> 2, cp = (lane & 3) * 2;
#pragma unroll
    for (int mi = 0; mi < 2; mi++) {
#pragma unroll
        for (int nj = 0; nj < 4; nj++) {
            int row = gm + mi * 16 + r;
            int col = gn + nj * 8 + cp;
            float v0 = acc[mi][nj][0], v1 = acc[mi][nj][1];
            float v2 = acc[mi][nj][2], v3 = acc[mi][nj][3];
            if (second) {
                float2 bb = *reinterpret_cast<const float2*>(&bias[col]);
                v0 = dt_transform(v0, bb.x);
                v1 = dt_transform(v1, bb.y);
                v2 = dt_transform(v2, bb.x);
                v3 = dt_transform(v3, bb.y);
            }
            *reinterpret_cast<float2*>(&C[(size_t)row * N + col]) = make_float2(v0, v1);
            *reinterpret_cast<float2*>(&C[(size_t)(row + 8) * N + col]) = make_float2(v2, v3);
        }
    }
}

// ---------------- B/C projection + row normalization ----------------
__global__ __launch_bounds__(128) void bc_kernel(const float* __restrict__ X,
                                                 const float* __restrict__ WB,
                                                 const float* __restrict__ WC) {
    int warp = threadIdx.x >> 5;
    int lane = threadIdx.x & 31;
    int m = blockIdx.x * 4 + warp;
    const float* Wr = (lane < 16) ? (WB + (size_t)lane * CDMODEL)
                                  : (WC + (size_t)(lane - 16) * CDMODEL);
    const float* Xr = X + (size_t)m * CDMODEL;

    float4 av = make_float4(0.f, 0.f, 0.f, 0.f);
    for (int k = 0; k < CDMODEL; k += 4) {
        float4 xv = *reinterpret_cast<const float4*>(&Xr[k]);
        float4 wv = *reinterpret_cast<const float4*>(&Wr[k]);
        av.x = fmaf(xv.x, wv.x, av.x);
        av.y = fmaf(xv.y, wv.y, av.y);
        av.z = fmaf(xv.z, wv.z, av.z);
        av.w = fmaf(xv.w, wv.w, av.w);
    }
    float acc = (av.x + av.y) + (av.z + av.w);

    float ss = acc * acc;
#pragma unroll
    for (int off = 8; off >= 1; off >>= 1)
        ss += __shfl_xor_sync(0xffffffffu, ss, off);
    float scale = 1.0f / fmaxf(sqrtf(ss), 1.0f);
    float v = acc * scale;
    if (lane < 16) g_Bn[(size_t)m * 16 + lane] = v;
    else           g_Cn[(size_t)m * 16 + (lane - 16)] = v;
}

__device__ __forceinline__ void load16(const float* p, float* v) {
    const float4* q = reinterpret_cast<const float4*>(p);
    float4 a = q[0], b = q[1], c = q[2], d = q[3];
    v[0] = a.x; v[1] = a.y; v[2] = a.z; v[3] = a.w;
    v[4] = b.x; v[5] = b.y; v[6] = b.z; v[7] = b.w;
    v[8] = c.x; v[9] = c.y; v[10] = c.z; v[11] = c.w;
    v[12] = d.x; v[13] = d.y; v[14] = d.z; v[15] = d.w;
}

__device__ __forceinline__ bool load_A(const float* __restrict__ A_log, int d, float* Av) {
    int head = d / CHEADDIM;
    bool fast = true;
#pragma unroll
    for (int n = 0; n < 16; n++) {
        Av[n] = expf(A_log[head * 16 + n]);
        if (fabsf(Av[n] - (float)(n + 1)) > 1e-3f * (float)(n + 1)) fast = false;
    }
    return fast;
}

// ---------------- scan pass 1 ----------------
__global__ __launch_bounds__(256) void scan_pass1(const float* __restrict__ A_log) {
    int d = blockIdx.x * 256 + threadIdx.x;
    int c = blockIdx.y;
    int b = blockIdx.z;

    float Av[16];
    bool fastA = load_A(A_log, d, Av);

    float h[16];
#pragma unroll
    for (int n = 0; n < 16; n++) h[n] = 0.0f;
    float S = 0.0f;

    int row0 = b * CSEQ + c * CLCHUNK;
    for (int t = 0; t < CLCHUNK; t++) {
        size_t ro = (size_t)(row0 + t) * CDMAMBA + d;
        float dt = g_dt[ro];
        float x  = g_xssm[ro];
        float Bv[16];
        load16(g_Bn + (size_t)(row0 + t) * 16, Bv);
        S += dt;
        float dtx = dt * x;
        if (fastA) {
            float r = __expf(-dt), p = 1.0f;
#pragma unroll
            for (int n = 0; n < 16; n++) { p *= r; h[n] = fmaf(p, h[n], dtx * Bv[n]); }
        } else {
#pragma unroll
            for (int n = 0; n < 16; n++) {
                float dec = __expf(-dt * Av[n]);
                h[n] = fmaf(dec, h[n], dtx * Bv[n]);
            }
        }
    }
    size_t base = ((size_t)(b * CNCHUNK + c) * 16) * CDMAMBA + d;
#pragma unroll
    for (int n = 0; n < 16; n++) g_hloc[base + (size_t)n * CDMAMBA] = h[n];
    g_S[(size_t)(b * CNCHUNK + c) * CDMAMBA + d] = S;
}

// ---------------- scan pass 2 ----------------
__global__ __launch_bounds__(256) void scan_pass2(const float* __restrict__ A_log) {
    int idx = blockIdx.x * 256 + threadIdx.x;
    int b = idx / CDMAMBA;
    int d = idx % CDMAMBA;

    float Av[16];
    bool fastA = load_A(A_log, d, Av);

    float h[16];
#pragma unroll
    for (int n = 0; n < 16; n++) h[n] = 0.0f;

    for (int c = 0; c < CNCHUNK; c++) {
        size_t base = ((size_t)(b * CNCHUNK + c) * 16) * CDMAMBA + d;
#pragma unroll
        for (int n = 0; n < 16; n++) g_hinit[base + (size_t)n * CDMAMBA] = h[n];
        float S = g_S[(size_t)(b * CNCHUNK + c) * CDMAMBA + d];
        if (fastA) {
            float R = __expf(-S), p = 1.0f;
#pragma unroll
            for (int n = 0; n < 16; n++) {
                p *= R;
                h[n] = fmaf(p, h[n], g_hloc[base + (size_t)n * CDMAMBA]);
            }
        } else {
#pragma unroll
            for (int n = 0; n < 16; n++) {
                float P = __expf(-S * Av[n]);
                h[n] = fmaf(P, h[n], g_hloc[base + (size_t)n * CDMAMBA]);
            }
        }
    }
}

// ---------------- scan pass 3: emit y as fp16 split ----------------
__global__ __launch_bounds__(256) void scan_pass3(const float* __restrict__ A_log,
                                                  const float* __restrict__ Dvec) {
    int d = blockIdx.x * 256 + threadIdx.x;
    int c = blockIdx.y;
    int b = blockIdx.z;

    float Av[16];
    bool fastA = load_A(A_log, d, Av);
    float Dd = Dvec[d];

    float h[16];
    size_t base = ((size_t)(b * CNCHUNK + c) * 16) * CDMAMBA + d;
#pragma unroll
    for (int n = 0; n < 16; n++) h[n] = g_hinit[base + (size_t)n * CDMAMBA];

    int row0 = b * CSEQ + c * CLCHUNK;
    for (int t = 0; t < CLCHUNK; t++) {
        size_t ro = (size_t)(row0 + t) * CDMAMBA + d;
        float dt = g_dt[ro];
        float x  = g_xssm[ro];
        float Bv[16], Cv[16];
        load16(g_Bn + (size_t)(row0 + t) * 16, Bv);
        load16(g_Cn + (size_t)(row0 + t) * 16, Cv);
        float dtx = dt * x;
        float y = 0.0f;
        if (fastA) {
            float r = __expf(-dt), p = 1.0f;
#pragma unroll
            for (int n = 0; n < 16; n++) {
                p *= r;
                h[n] = fmaf(p, h[n], dtx * Bv[n]);
                y = fmaf(h[n], Cv[n], y);
            }
        } else {
#pragma unroll
            for (int n = 0; n < 16; n++) {
                float dec = __expf(-dt * Av[n]);
                h[n] = fmaf(dec, h[n], dtx * Bv[n]);
                y = fmaf(h[n], Cv[n], y);
            }
        }
        float yv = fmaf(x, Dd, y);
        ushort_t yh, yl;
        split1(yv, yh, yl);
        g_y_h[ro] = yh;
        g_y_l[ro] = yl;
    }
}

// ---------------- launch ----------------
extern "C" void kernel_launch(void* const* d_in, const int* in_sizes, int n_in,
                              void* d_out, int out_size) {
    (void)in_sizes; (void)n_in; (void)out_size;
    const float* x_norm     = (const float*)d_in[0];
    const float* x_proj_w   = (const float*)d_in[1];
    const float* dt_proj_w  = (const float*)d_in[2];
    const float* dt_proj_b  = (const float*)d_in[3];
    const float* B_proj_w   = (const float*)d_in[4];
    const float* C_proj_w   = (const float*)d_in[5];
    const float* A_log      = (const float*)d_in[6];
    const float* Dvec       = (const float*)d_in[7];
    const float* out_proj_w = (const float*)d_in[8];
    float* out = (float*)d_out;

    void *p_xssm, *p_dt;
    void *p_xnh, *p_xnl, *p_w1h, *p_w2h, *p_w3h, *p_yh, *p_yl;
    cudaGetSymbolAddress(&p_xssm, g_xssm);
    cudaGetSymbolAddress(&p_dt, g_dt);
    cudaGetSymbolAddress(&p_xnh, g_xn_h);  cudaGetSymbolAddress(&p_xnl, g_xn_l);
    cudaGetSymbolAddress(&p_w1h, g_w1_h);
    cudaGetSymbolAddress(&p_w2h, g_w2_h);
    cudaGetSymbolAddress(&p_w3h, g_w3_h);
    cudaGetSymbolAddress(&p_yh, g_y_h);    cudaGetSymbolAddress(&p_yl, g_y_l);

    cudaFuncSetAttribute(gemm_mma, cudaFuncAttributeMaxDynamicSharedMemorySize, SM_TOTAL);

    // fp16 split of x_norm; fp16-hi of the three GEMM weights
    {
        int n4 = (CMROWS * CDMODEL) / 4;
        conv_split<<<n4 / 256, 256>>>(x_norm, (ushort_t*)p_xnh, (ushort_t*)p_xnl, n4);
        n4 = (CDMAMBA * CDMODEL) / 4;
        conv_h<<<n4 / 256, 256>>>(x_proj_w, (ushort_t*)p_w1h, n4);
        conv_h<<<n4 / 256, 256>>>(dt_proj_w, (ushort_t*)p_w2h, n4);
        n4 = (CDMAMBA * CDMAMBA) / 4;
        conv_h<<<n4 / 256, 256>>>(out_proj_w, (ushort_t*)p_w3h, n4);
    }

    // 1+2) fused: x_ssm = x_norm @ W1^T ; dt = dt_transform(x_norm @ W2^T + b)
    {
        dim3 grid(2 * (CDMAMBA / 128), CMROWS / 128);   // (32, 64)
        gemm_mma<<<grid, 512, SM_TOTAL>>>(
            (const ushort_t*)p_xnh, (const ushort_t*)p_xnl,
            (const ushort_t*)p_w1h, (const ushort_t*)p_w2h, dt_proj_b,
            (float*)p_xssm, (float*)p_dt,
            CDMAMBA / 128, CDMAMBA, CDMODEL);
    }
    // 3) normalized B, C
    bc_kernel<<<CMROWS / 4, 128>>>(x_norm, B_proj_w, C_proj_w);
    // 4-6) chunked selective scan (pass3 emits y split into fp16 hi/lo)
    dim3 scan_grid(CDMAMBA / 256, CNCHUNK, CBATCH);
    scan_pass1<<<scan_grid, 256>>>(A_log);
    scan_pass2<<<(CBATCH * CDMAMBA) / 256, 256>>>(A_log);
    scan_pass3<<<scan_grid, 256>>>(A_log, Dvec);
    // 7) out = y @ out_proj_w^T
    {
        dim3 grid(CDMAMBA / 128, CMROWS / 128);   // (16, 64)
        gemm_mma<<<grid, 512, SM_TOTAL>>>(
            (const ushort_t*)p_yh, (const ushort_t*)p_yl,
            (const ushort_t*)p_w3h, (const ushort_t*)p_w3h, nullptr,
            out, out,
            CDMAMBA / 128, CDMAMBA, CDMAMBA);
    }
}

// round 6
// speedup vs baseline: 1.6356x; 1.6356x over previous
#include <cuda_runtime.h>
#include <cuda_fp16.h>
#include <math.h>
#include <stdint.h>

#define CBATCH   4
#define CSEQ     2048
#define CDMODEL  1024
#define CDMAMBA  2048
#define CDSTATE  16
#define CNHEADS  32
#define CMROWS   (CBATCH * CSEQ)          // 8192
#define CNCHUNK  32
#define CLCHUNK  (CSEQ / CNCHUNK)         // 64
#define CHEADDIM (CDMAMBA / CNHEADS)      // 64
#define CHALF    (CDMAMBA / 2)            // 1024

typedef unsigned short ushort_t;

// ---------------- scratch (static device arrays; no runtime allocation) ----------------
__device__ float g_xssm[CMROWS * CDMAMBA];
__device__ float g_dt  [CMROWS * CDMAMBA];
__device__ float g_Bn  [CMROWS * CDSTATE];
__device__ float g_Cn  [CMROWS * CDSTATE];
__device__ float g_hloc [CBATCH * CNCHUNK * CDSTATE * CDMAMBA];
__device__ float g_hinit[CBATCH * CNCHUNK * CDSTATE * CDMAMBA];
__device__ float g_S    [CBATCH * CNCHUNK * CDMAMBA];

// fp16 split operands: A-side hi+lo, W-side hi only
__device__ ushort_t g_xn_h[CMROWS * CDMODEL];
__device__ ushort_t g_xn_l[CMROWS * CDMODEL];
__device__ ushort_t g_w1_h[CDMAMBA * CDMODEL];
__device__ ushort_t g_w2_h[CDMAMBA * CDMODEL];
__device__ ushort_t g_w3_h[CDMAMBA * CDMAMBA];
__device__ ushort_t g_y_h[CMROWS * CDMAMBA];
__device__ ushort_t g_y_l[CMROWS * CDMAMBA];

// ---------------- PTX helpers (baseline sm_80-level features only) ----------------
__device__ __forceinline__ uint32_t smem_u32(const void* p) {
    uint32_t a;
    asm("{ .reg .u64 t; cvta.to.shared.u64 t, %1; cvt.u32.u64 %0, t; }" : "=r"(a) : "l"(p));
    return a;
}

#define CP_ASYNC16(dst, src) \
    asm volatile("cp.async.cg.shared.global [%0], [%1], 16;" :: "r"(dst), "l"(src))
#define CP_COMMIT() asm volatile("cp.async.commit_group;" ::: "memory")
#define CP_WAIT0() asm volatile("cp.async.wait_group 0;" ::: "memory")
#define CP_WAIT1() asm volatile("cp.async.wait_group 1;" ::: "memory")

#define LDSM4(r, addr) \
    asm volatile("ldmatrix.sync.aligned.m8n8.x4.shared.b16 {%0,%1,%2,%3}, [%4];" \
        : "=r"((r)[0]), "=r"((r)[1]), "=r"((r)[2]), "=r"((r)[3]) : "r"(addr))

#define MMA_F16(d, a, b0, b1) \
    asm volatile("mma.sync.aligned.m16n8k16.row.col.f32.f16.f16.f32 " \
        "{%0,%1,%2,%3}, {%4,%5,%6,%7}, {%8,%9}, {%0,%1,%2,%3};" \
        : "+f"((d)[0]), "+f"((d)[1]), "+f"((d)[2]), "+f"((d)[3]) \
        : "r"((a)[0]), "r"((a)[1]), "r"((a)[2]), "r"((a)[3]), "r"(b0), "r"(b1))

__device__ __forceinline__ uint32_t swz(uint32_t off) {   // SW128 xor swizzle
    return off ^ ((off >> 3) & 0x70);
}

// ---------------- fp16 split conversion ----------------
__device__ __forceinline__ void split1(float v, ushort_t& h, ushort_t& l) {
    __half hh = __float2half(v);
    h = __half_as_ushort(hh);
    l = __half_as_ushort(__float2half(v - __half2float(hh)));
}

__global__ __launch_bounds__(256) void conv_split(const float* __restrict__ in,
                                                  ushort_t* __restrict__ hi,
                                                  ushort_t* __restrict__ lo,
                                                  int n4) {
    int i = blockIdx.x * 256 + threadIdx.x;
    if (i >= n4) return;
    float4 v = reinterpret_cast<const float4*>(in)[i];
    ushort4 h, l;
    split1(v.x, h.x, l.x);
    split1(v.y, h.y, l.y);
    split1(v.z, h.z, l.z);
    split1(v.w, h.w, l.w);
    reinterpret_cast<ushort4*>(hi)[i] = h;
    reinterpret_cast<ushort4*>(lo)[i] = l;
}

__global__ __launch_bounds__(256) void conv_h(const float* __restrict__ in,
                                              ushort_t* __restrict__ hi, int n4) {
    int i = blockIdx.x * 256 + threadIdx.x;
    if (i >= n4) return;
    float4 v = reinterpret_cast<const float4*>(in)[i];
    ushort4 h;
    h.x = __half_as_ushort(__float2half(v.x));
    h.y = __half_as_ushort(__float2half(v.y));
    h.z = __half_as_ushort(__float2half(v.z));
    h.w = __half_as_ushort(__float2half(v.w));
    reinterpret_cast<ushort4*>(hi)[i] = h;
}

__device__ __forceinline__ float dt_transform(float v, float b) {
    v += b;
    v = fminf(fmaxf(v, -10.0f), 5.0f);
    v = log1pf(expf(v));
    return fminf(fmaxf(v, 1e-4f), 0.1f);
}

// ---------------- HMMA fp16x2 GEMM (R4 geometry: 256 thr, 2 CTA/SM, 2-stage) ----------------
// C[m,n] = sum_k A[m,k]*W[n,k] ~= (Ah+Al)[m,:]*Wh[n,:]; tile 128x128, BK=64,
// 8 warps (4x2), 32x64 warp tiles. 2 stages x 48KB = 96KB/CTA.
#define TILE_B   16384
#define STAGE_B  49152
#define SM_TOTAL (2 * STAGE_B)   // 98304

__device__ __forceinline__ void stage_load(
    const ushort_t* __restrict__ Ah, const ushort_t* __restrict__ Al,
    const ushort_t* __restrict__ Wh,
    uint32_t sbase, int m0, int n0, int kc, int K, int tid) {
#pragma unroll
    for (int tile = 0; tile < 3; tile++) {
        const ushort_t* g = (tile == 0) ? Ah : (tile == 1) ? Al : Wh;
        int row0 = (tile < 2) ? m0 : n0;
#pragma unroll
        for (int j = 0; j < 4; j++) {
            int idx = tid + j * 256;           // 0..1023
            int row = idx >> 3, seg = idx & 7;
            const ushort_t* src = g + (size_t)(row0 + row) * K + kc + seg * 8;
            uint32_t dst = sbase + tile * TILE_B + swz((uint32_t)(row * 128 + seg * 16));
            CP_ASYNC16(dst, src);
        }
    }
}

__device__ __forceinline__ void stage_compute(uint32_t sbase, int wm, int wn,
                                              int lane, float acc[2][8][4]) {
    const uint32_t aAh = sbase;
    const uint32_t aAl = sbase + TILE_B;
    const uint32_t aWh = sbase + 2 * TILE_B;
    const int arow = wm + (lane & 15);
    const int akb  = (lane >> 4) * 16;
    const int brow = wn + ((lane >> 4) << 3) + (lane & 7);
    const int bkb  = ((lane >> 3) & 1) * 16;

#pragma unroll
    for (int ks = 0; ks < 4; ks++) {
        const int kb = ks * 32;
        uint32_t ah[2][4], al[2][4];
#pragma unroll
        for (int mi = 0; mi < 2; mi++) {
            uint32_t off = swz((uint32_t)((arow + mi * 16) * 128 + akb + kb));
            LDSM4(ah[mi], aAh + off);
            LDSM4(al[mi], aAl + off);
        }
        uint32_t bh[4][4];
#pragma unroll
        for (int ni = 0; ni < 4; ni++) {
            uint32_t off = swz((uint32_t)((brow + ni * 16) * 128 + bkb + kb));
            LDSM4(bh[ni], aWh + off);
        }
#pragma unroll
        for (int mi = 0; mi < 2; mi++) {
#pragma unroll
            for (int ni = 0; ni < 4; ni++) {
                MMA_F16(acc[mi][2 * ni + 0], ah[mi], bh[ni][0], bh[ni][1]);
                MMA_F16(acc[mi][2 * ni + 0], al[mi], bh[ni][0], bh[ni][1]);
                MMA_F16(acc[mi][2 * ni + 1], ah[mi], bh[ni][2], bh[ni][3]);
                MMA_F16(acc[mi][2 * ni + 1], al[mi], bh[ni][2], bh[ni][3]);
            }
        }
    }
}

// Blocks with blockIdx.x < n1blk: C1 = A*W1^T (identity epilogue).
// Blocks with blockIdx.x >= n1blk: C2 = dt_transform(A*W2^T + bias).
__global__ __launch_bounds__(256, 2) void gemm_mma(
    const ushort_t* __restrict__ Ah, const ushort_t* __restrict__ Al,
    const ushort_t* __restrict__ W1, const ushort_t* __restrict__ W2,
    const float* __restrict__ bias, float* __restrict__ C1, float* __restrict__ C2,
    int n1blk, int N, int K) {
    extern __shared__ __align__(1024) char smem[];
    const uint32_t sb = smem_u32(smem);
    const int tid = threadIdx.x, lane = tid & 31, w = tid >> 5;
    const int m0 = blockIdx.y * 128;
    const bool second = ((int)blockIdx.x >= n1blk);
    const int n0 = (second ? (int)blockIdx.x - n1blk : (int)blockIdx.x) * 128;
    const ushort_t* Wh = second ? W2 : W1;
    float* C = second ? C2 : C1;
    const int wm = (w & 3) * 32, wn = (w >> 2) * 64;
    const int NC = K >> 6;

    float acc[2][8][4];
#pragma unroll
    for (int i = 0; i < 2; i++)
#pragma unroll
        for (int j = 0; j < 8; j++)
#pragma unroll
            for (int q = 0; q < 4; q++) acc[i][j][q] = 0.0f;

    stage_load(Ah, Al, Wh, sb + 0 * STAGE_B, m0, n0, 0, K, tid);  CP_COMMIT();
    stage_load(Ah, Al, Wh, sb + 1 * STAGE_B, m0, n0, 64, K, tid); CP_COMMIT();

    for (int c = 0; c < NC; c++) {
        if (c + 1 < NC) { CP_WAIT1(); } else { CP_WAIT0(); }
        __syncthreads();
        const uint32_t stage = sb + (c & 1) * STAGE_B;
        stage_compute(stage, wm, wn, lane, acc);
        __syncthreads();
        if (c + 2 < NC) {
            stage_load(Ah, Al, Wh, stage, m0, n0, (c + 2) * 64, K, tid);
            CP_COMMIT();
        }
    }

    // epilogue
    const int gm = m0 + wm, gn = n0 + wn;
    const int r = lane >> 2, cp = (lane & 3) * 2;
#pragma unroll
    for (int mi = 0; mi < 2; mi++) {
#pragma unroll
        for (int nj = 0; nj < 8; nj++) {
            int row = gm + mi * 16 + r;
            int col = gn + nj * 8 + cp;
            float v0 = acc[mi][nj][0], v1 = acc[mi][nj][1];
            float v2 = acc[mi][nj][2], v3 = acc[mi][nj][3];
            if (second) {
                float2 bb = *reinterpret_cast<const float2*>(&bias[col]);
                v0 = dt_transform(v0, bb.x);
                v1 = dt_transform(v1, bb.y);
                v2 = dt_transform(v2, bb.x);
                v3 = dt_transform(v3, bb.y);
            }
            *reinterpret_cast<float2*>(&C[(size_t)row * N + col]) = make_float2(v0, v1);
            *reinterpret_cast<float2*>(&C[(size_t)(row + 8) * N + col]) = make_float2(v2, v3);
        }
    }
}

// ---------------- B/C projection + row normalization ----------------
__global__ __launch_bounds__(128) void bc_kernel(const float* __restrict__ X,
                                                 const float* __restrict__ WB,
                                                 const float* __restrict__ WC) {
    int warp = threadIdx.x >> 5;
    int lane = threadIdx.x & 31;
    int m = blockIdx.x * 4 + warp;
    const float* Wr = (lane < 16) ? (WB + (size_t)lane * CDMODEL)
                                  : (WC + (size_t)(lane - 16) * CDMODEL);
    const float* Xr = X + (size_t)m * CDMODEL;

    float4 av = make_float4(0.f, 0.f, 0.f, 0.f);
    for (int k = 0; k < CDMODEL; k += 4) {
        float4 xv = *reinterpret_cast<const float4*>(&Xr[k]);
        float4 wv = *reinterpret_cast<const float4*>(&Wr[k]);
        av.x = fmaf(xv.x, wv.x, av.x);
        av.y = fmaf(xv.y, wv.y, av.y);
        av.z = fmaf(xv.z, wv.z, av.z);
        av.w = fmaf(xv.w, wv.w, av.w);
    }
    float acc = (av.x + av.y) + (av.z + av.w);

    float ss = acc * acc;
#pragma unroll
    for (int off = 8; off >= 1; off >>= 1)
        ss += __shfl_xor_sync(0xffffffffu, ss, off);
    float scale = 1.0f / fmaxf(sqrtf(ss), 1.0f);
    float v = acc * scale;
    if (lane < 16) g_Bn[(size_t)m * 16 + lane] = v;
    else           g_Cn[(size_t)m * 16 + (lane - 16)] = v;
}

__device__ __forceinline__ void load16(const float* p, float* v) {
    const float4* q = reinterpret_cast<const float4*>(p);
    float4 a = q[0], b = q[1], c = q[2], d = q[3];
    v[0] = a.x; v[1] = a.y; v[2] = a.z; v[3] = a.w;
    v[4] = b.x; v[5] = b.y; v[6] = b.z; v[7] = b.w;
    v[8] = c.x; v[9] = c.y; v[10] = c.z; v[11] = c.w;
    v[12] = d.x; v[13] = d.y; v[14] = d.z; v[15] = d.w;
}

__device__ __forceinline__ bool load_A(const float* __restrict__ A_log, int d, float* Av) {
    int head = d / CHEADDIM;
    bool fast = true;
#pragma unroll
    for (int n = 0; n < 16; n++) {
        Av[n] = expf(A_log[head * 16 + n]);
        if (fabsf(Av[n] - (float)(n + 1)) > 1e-3f * (float)(n + 1)) fast = false;
    }
    return fast;
}

// ---------------- scan pass 1: 2 channels/thread (d and d+1024) ----------------
__global__ __launch_bounds__(256) void scan_pass1(const float* __restrict__ A_log) {
    int d0 = blockIdx.x * 256 + threadIdx.x;   // 0..1023
    int d1 = d0 + CHALF;
    int c = blockIdx.y;
    int b = blockIdx.z;

    float Av0[16], Av1[16];
    bool fastA = load_A(A_log, d0, Av0) && load_A(A_log, d1, Av1);

    float h0[16], h1[16];
#pragma unroll
    for (int n = 0; n < 16; n++) { h0[n] = 0.0f; h1[n] = 0.0f; }
    float S0 = 0.0f, S1 = 0.0f;

    int row0 = b * CSEQ + c * CLCHUNK;
    for (int t = 0; t < CLCHUNK; t++) {
        size_t ro = (size_t)(row0 + t) * CDMAMBA + d0;
        float dt0 = g_dt[ro],         x0 = g_xssm[ro];
        float dt1 = g_dt[ro + CHALF], x1 = g_xssm[ro + CHALF];
        float Bv[16];
        load16(g_Bn + (size_t)(row0 + t) * 16, Bv);
        S0 += dt0; S1 += dt1;
        float dtx0 = dt0 * x0, dtx1 = dt1 * x1;
        if (fastA) {
            float r0 = __expf(-dt0), p0 = 1.0f;
            float r1 = __expf(-dt1), p1 = 1.0f;
#pragma unroll
            for (int n = 0; n < 16; n++) {
                p0 *= r0; h0[n] = fmaf(p0, h0[n], dtx0 * Bv[n]);
                p1 *= r1; h1[n] = fmaf(p1, h1[n], dtx1 * Bv[n]);
            }
        } else {
#pragma unroll
            for (int n = 0; n < 16; n++) {
                h0[n] = fmaf(__expf(-dt0 * Av0[n]), h0[n], dtx0 * Bv[n]);
                h1[n] = fmaf(__expf(-dt1 * Av1[n]), h1[n], dtx1 * Bv[n]);
            }
        }
    }
    size_t base = ((size_t)(b * CNCHUNK + c) * 16) * CDMAMBA + d0;
#pragma unroll
    for (int n = 0; n < 16; n++) {
        g_hloc[base + (size_t)n * CDMAMBA] = h0[n];
        g_hloc[base + (size_t)n * CDMAMBA + CHALF] = h1[n];
    }
    g_S[(size_t)(b * CNCHUNK + c) * CDMAMBA + d0] = S0;
    g_S[(size_t)(b * CNCHUNK + c) * CDMAMBA + d1] = S1;
}

// ---------------- scan pass 2 ----------------
__global__ __launch_bounds__(256) void scan_pass2(const float* __restrict__ A_log) {
    int idx = blockIdx.x * 256 + threadIdx.x;
    int b = idx / CDMAMBA;
    int d = idx % CDMAMBA;

    float Av[16];
    bool fastA = load_A(A_log, d, Av);

    float h[16];
#pragma unroll
    for (int n = 0; n < 16; n++) h[n] = 0.0f;

    for (int c = 0; c < CNCHUNK; c++) {
        size_t base = ((size_t)(b * CNCHUNK + c) * 16) * CDMAMBA + d;
#pragma unroll
        for (int n = 0; n < 16; n++) g_hinit[base + (size_t)n * CDMAMBA] = h[n];
        float S = g_S[(size_t)(b * CNCHUNK + c) * CDMAMBA + d];
        if (fastA) {
            float R = __expf(-S), p = 1.0f;
#pragma unroll
            for (int n = 0; n < 16; n++) {
                p *= R;
                h[n] = fmaf(p, h[n], g_hloc[base + (size_t)n * CDMAMBA]);
            }
        } else {
#pragma unroll
            for (int n = 0; n < 16; n++) {
                float P = __expf(-S * Av[n]);
                h[n] = fmaf(P, h[n], g_hloc[base + (size_t)n * CDMAMBA]);
            }
        }
    }
}

// ---------------- scan pass 3: 2 channels/thread, emit y as fp16 split ----------------
__global__ __launch_bounds__(256) void scan_pass3(const float* __restrict__ A_log,
                                                  const float* __restrict__ Dvec) {
    int d0 = blockIdx.x * 256 + threadIdx.x;   // 0..1023
    int d1 = d0 + CHALF;
    int c = blockIdx.y;
    int b = blockIdx.z;

    float Av0[16], Av1[16];
    bool fastA = load_A(A_log, d0, Av0) && load_A(A_log, d1, Av1);
    float Dd0 = Dvec[d0], Dd1 = Dvec[d1];

    float h0[16], h1[16];
    size_t base = ((size_t)(b * CNCHUNK + c) * 16) * CDMAMBA + d0;
#pragma unroll
    for (int n = 0; n < 16; n++) {
        h0[n] = g_hinit[base + (size_t)n * CDMAMBA];
        h1[n] = g_hinit[base + (size_t)n * CDMAMBA + CHALF];
    }

    int row0 = b * CSEQ + c * CLCHUNK;
    for (int t = 0; t < CLCHUNK; t++) {
        size_t ro = (size_t)(row0 + t) * CDMAMBA + d0;
        float dt0 = g_dt[ro],         x0 = g_xssm[ro];
        float dt1 = g_dt[ro + CHALF], x1 = g_xssm[ro + CHALF];
        float Bv[16], Cv[16];
        load16(g_Bn + (size_t)(row0 + t) * 16, Bv);
        load16(g_Cn + (size_t)(row0 + t) * 16, Cv);
        float dtx0 = dt0 * x0, dtx1 = dt1 * x1;
        float y0 = 0.0f, y1 = 0.0f;
        if (fastA) {
            float r0 = __expf(-dt0), p0 = 1.0f;
            float r1 = __expf(-dt1), p1 = 1.0f;
#pragma unroll
            for (int n = 0; n < 16; n++) {
                p0 *= r0; h0[n] = fmaf(p0, h0[n], dtx0 * Bv[n]); y0 = fmaf(h0[n], Cv[n], y0);
                p1 *= r1; h1[n] = fmaf(p1, h1[n], dtx1 * Bv[n]); y1 = fmaf(h1[n], Cv[n], y1);
            }
        } else {
#pragma unroll
            for (int n = 0; n < 16; n++) {
                h0[n] = fmaf(__expf(-dt0 * Av0[n]), h0[n], dtx0 * Bv[n]); y0 = fmaf(h0[n], Cv[n], y0);
                h1[n] = fmaf(__expf(-dt1 * Av1[n]), h1[n], dtx1 * Bv[n]); y1 = fmaf(h1[n], Cv[n], y1);
            }
        }
        float yv0 = fmaf(x0, Dd0, y0);
        float yv1 = fmaf(x1, Dd1, y1);
        ushort_t yh, yl;
        split1(yv0, yh, yl);
        g_y_h[ro] = yh; g_y_l[ro] = yl;
        split1(yv1, yh, yl);
        g_y_h[ro + CHALF] = yh; g_y_l[ro + CHALF] = yl;
    }
}

// ---------------- launch ----------------
extern "C" void kernel_launch(void* const* d_in, const int* in_sizes, int n_in,
                              void* d_out, int out_size) {
    (void)in_sizes; (void)n_in; (void)out_size;
    const float* x_norm     = (const float*)d_in[0];
    const float* x_proj_w   = (const float*)d_in[1];
    const float* dt_proj_w  = (const float*)d_in[2];
    const float* dt_proj_b  = (const float*)d_in[3];
    const float* B_proj_w   = (const float*)d_in[4];
    const float* C_proj_w   = (const float*)d_in[5];
    const float* A_log      = (const float*)d_in[6];
    const float* Dvec       = (const float*)d_in[7];
    const float* out_proj_w = (const float*)d_in[8];
    float* out = (float*)d_out;

    void *p_xssm, *p_dt;
    void *p_xnh, *p_xnl, *p_w1h, *p_w2h, *p_w3h, *p_yh, *p_yl;
    cudaGetSymbolAddress(&p_xssm, g_xssm);
    cudaGetSymbolAddress(&p_dt, g_dt);
    cudaGetSymbolAddress(&p_xnh, g_xn_h);  cudaGetSymbolAddress(&p_xnl, g_xn_l);
    cudaGetSymbolAddress(&p_w1h, g_w1_h);
    cudaGetSymbolAddress(&p_w2h, g_w2_h);
    cudaGetSymbolAddress(&p_w3h, g_w3_h);
    cudaGetSymbolAddress(&p_yh, g_y_h);    cudaGetSymbolAddress(&p_yl, g_y_l);

    cudaFuncSetAttribute(gemm_mma, cudaFuncAttributeMaxDynamicSharedMemorySize, SM_TOTAL);

    // fp16 split of x_norm; fp16-hi of the three GEMM weights
    {
        int n4 = (CMROWS * CDMODEL) / 4;
        conv_split<<<n4 / 256, 256>>>(x_norm, (ushort_t*)p_xnh, (ushort_t*)p_xnl, n4);
        n4 = (CDMAMBA * CDMODEL) / 4;
        conv_h<<<n4 / 256, 256>>>(x_proj_w, (ushort_t*)p_w1h, n4);
        conv_h<<<n4 / 256, 256>>>(dt_proj_w, (ushort_t*)p_w2h, n4);
        n4 = (CDMAMBA * CDMAMBA) / 4;
        conv_h<<<n4 / 256, 256>>>(out_proj_w, (ushort_t*)p_w3h, n4);
    }

    // 1+2) fused: x_ssm = x_norm @ W1^T ; dt = dt_transform(x_norm @ W2^T + b)
    {
        dim3 grid(2 * (CDMAMBA / 128), CMROWS / 128);   // (32, 64)
        gemm_mma<<<grid, 256, SM_TOTAL>>>(
            (const ushort_t*)p_xnh, (const ushort_t*)p_xnl,
            (const ushort_t*)p_w1h, (const ushort_t*)p_w2h, dt_proj_b,
            (float*)p_xssm, (float*)p_dt,
            CDMAMBA / 128, CDMAMBA, CDMODEL);
    }
    // 3) normalized B, C
    bc_kernel<<<CMROWS / 4, 128>>>(x_norm, B_proj_w, C_proj_w);
    // 4-6) chunked selective scan (2 channels per thread in pass1/pass3)
    dim3 scan_grid(CHALF / 256, CNCHUNK, CBATCH);   // (4, 32, 4)
    scan_pass1<<<scan_grid, 256>>>(A_log);
    scan_pass2<<<(CBATCH * CDMAMBA) / 256, 256>>>(A_log);
    scan_pass3<<<scan_grid, 256>>>(A_log, Dvec);
    // 7) out = y @ out_proj_w^T
    {
        dim3 grid(CDMAMBA / 128, CMROWS / 128);   // (16, 64)
        gemm_mma<<<grid, 256, SM_TOTAL>>>(
            (const ushort_t*)p_yh, (const ushort_t*)p_yl,
            (const ushort_t*)p_w3h, (const ushort_t*)p_w3h, nullptr,
            out, out,
            CDMAMBA / 128, CDMAMBA, CDMAMBA);
    }
}

// round 7
// speedup vs baseline: 2.1097x; 1.2899x over previous
#include <cuda_runtime.h>
#include <cuda_fp16.h>
#include <math.h>
#include <stdint.h>

#define CBATCH   4
#define CSEQ     2048
#define CDMODEL  1024
#define CDMAMBA  2048
#define CDSTATE  16
#define CNHEADS  32
#define CMROWS   (CBATCH * CSEQ)          // 8192
#define CNCHUNK  32
#define CLCHUNK  (CSEQ / CNCHUNK)         // 64
#define CHEADDIM (CDMAMBA / CNHEADS)      // 64
#define CHALF    (CDMAMBA / 2)            // 1024

typedef unsigned short ushort_t;

// ---------------- scratch (static device arrays; no runtime allocation) ----------------
__device__ float g_xssm[CMROWS * CDMAMBA];
__device__ float g_dt  [CMROWS * CDMAMBA];
__device__ float g_Bn  [CMROWS * CDSTATE];
__device__ float g_Cn  [CMROWS * CDSTATE];
__device__ float g_hloc [CBATCH * CNCHUNK * CDSTATE * CDMAMBA];
__device__ float g_hinit[CBATCH * CNCHUNK * CDSTATE * CDMAMBA];
__device__ float g_S    [CBATCH * CNCHUNK * CDMAMBA];

// fp16 operands (single hi term on both sides)
__device__ ushort_t g_xn_h[CMROWS * CDMODEL];
__device__ ushort_t g_w1_h[CDMAMBA * CDMODEL];
__device__ ushort_t g_w2_h[CDMAMBA * CDMODEL];
__device__ ushort_t g_w3_h[CDMAMBA * CDMAMBA];
__device__ ushort_t g_y_h[CMROWS * CDMAMBA];

// ---------------- PTX helpers (baseline sm_80-level features only) ----------------
__device__ __forceinline__ uint32_t smem_u32(const void* p) {
    uint32_t a;
    asm("{ .reg .u64 t; cvta.to.shared.u64 t, %1; cvt.u32.u64 %0, t; }" : "=r"(a) : "l"(p));
    return a;
}

#define CP_ASYNC16(dst, src) \
    asm volatile("cp.async.cg.shared.global [%0], [%1], 16;" :: "r"(dst), "l"(src))
#define CP_COMMIT() asm volatile("cp.async.commit_group;" ::: "memory")
#define CP_WAIT0() asm volatile("cp.async.wait_group 0;" ::: "memory")
#define CP_WAIT1() asm volatile("cp.async.wait_group 1;" ::: "memory")

#define LDSM4(r, addr) \
    asm volatile("ldmatrix.sync.aligned.m8n8.x4.shared.b16 {%0,%1,%2,%3}, [%4];" \
        : "=r"((r)[0]), "=r"((r)[1]), "=r"((r)[2]), "=r"((r)[3]) : "r"(addr))

#define MMA_F16(d, a, b0, b1) \
    asm volatile("mma.sync.aligned.m16n8k16.row.col.f32.f16.f16.f32 " \
        "{%0,%1,%2,%3}, {%4,%5,%6,%7}, {%8,%9}, {%0,%1,%2,%3};" \
        : "+f"((d)[0]), "+f"((d)[1]), "+f"((d)[2]), "+f"((d)[3]) \
        : "r"((a)[0]), "r"((a)[1]), "r"((a)[2]), "r"((a)[3]), "r"(b0), "r"(b1))

__device__ __forceinline__ uint32_t swz(uint32_t off) {   // SW128 xor swizzle
    return off ^ ((off >> 3) & 0x70);
}

// ---------------- fp16 conversion ----------------
__global__ __launch_bounds__(256) void conv_h(const float* __restrict__ in,
                                              ushort_t* __restrict__ hi, int n4) {
    int i = blockIdx.x * 256 + threadIdx.x;
    if (i >= n4) return;
    float4 v = reinterpret_cast<const float4*>(in)[i];
    ushort4 h;
    h.x = __half_as_ushort(__float2half(v.x));
    h.y = __half_as_ushort(__float2half(v.y));
    h.z = __half_as_ushort(__float2half(v.z));
    h.w = __half_as_ushort(__float2half(v.w));
    reinterpret_cast<ushort4*>(hi)[i] = h;
}

__device__ __forceinline__ float dt_transform(float v, float b) {
    v += b;
    v = fminf(fmaxf(v, -10.0f), 5.0f);
    v = log1pf(expf(v));
    return fminf(fmaxf(v, 1e-4f), 0.1f);
}

// ---------------- HMMA fp16 GEMM (R4 geometry, single term) ----------------
// C[m,n] = sum_k A[m,k]*W[n,k] ~= Ah[m,:]*Wh[n,:]; tile 128x128, BK=64,
// 8 warps (4x2), 32x64 warp tiles. 2 stages x 32KB = 64KB/CTA, 2 CTA/SM.
#define TILE_B   16384
#define STAGE_B  32768
#define SM_TOTAL (2 * STAGE_B)   // 65536

__device__ __forceinline__ void stage_load(
    const ushort_t* __restrict__ Ah, const ushort_t* __restrict__ Wh,
    uint32_t sbase, int m0, int n0, int kc, int K, int tid) {
#pragma unroll
    for (int tile = 0; tile < 2; tile++) {
        const ushort_t* g = (tile == 0) ? Ah : Wh;
        int row0 = (tile == 0) ? m0 : n0;
#pragma unroll
        for (int j = 0; j < 4; j++) {
            int idx = tid + j * 256;           // 0..1023
            int row = idx >> 3, seg = idx & 7;
            const ushort_t* src = g + (size_t)(row0 + row) * K + kc + seg * 8;
            uint32_t dst = sbase + tile * TILE_B + swz((uint32_t)(row * 128 + seg * 16));
            CP_ASYNC16(dst, src);
        }
    }
}

__device__ __forceinline__ void stage_compute(uint32_t sbase, int wm, int wn,
                                              int lane, float acc[2][8][4]) {
    const uint32_t aAh = sbase;
    const uint32_t aWh = sbase + TILE_B;
    const int arow = wm + (lane & 15);
    const int akb  = (lane >> 4) * 16;
    const int brow = wn + ((lane >> 4) << 3) + (lane & 7);
    const int bkb  = ((lane >> 3) & 1) * 16;

#pragma unroll
    for (int ks = 0; ks < 4; ks++) {
        const int kb = ks * 32;
        uint32_t ah[2][4];
#pragma unroll
        for (int mi = 0; mi < 2; mi++) {
            uint32_t off = swz((uint32_t)((arow + mi * 16) * 128 + akb + kb));
            LDSM4(ah[mi], aAh + off);
        }
        uint32_t bh[4][4];
#pragma unroll
        for (int ni = 0; ni < 4; ni++) {
            uint32_t off = swz((uint32_t)((brow + ni * 16) * 128 + bkb + kb));
            LDSM4(bh[ni], aWh + off);
        }
#pragma unroll
        for (int mi = 0; mi < 2; mi++) {
#pragma unroll
            for (int ni = 0; ni < 4; ni++) {
                MMA_F16(acc[mi][2 * ni + 0], ah[mi], bh[ni][0], bh[ni][1]);
                MMA_F16(acc[mi][2 * ni + 1], ah[mi], bh[ni][2], bh[ni][3]);
            }
        }
    }
}

// Blocks with blockIdx.x < n1blk: C1 = A*W1^T (identity epilogue).
// Blocks with blockIdx.x >= n1blk: C2 = dt_transform(A*W2^T + bias).
__global__ __launch_bounds__(256, 2) void gemm_mma(
    const ushort_t* __restrict__ Ah,
    const ushort_t* __restrict__ W1, const ushort_t* __restrict__ W2,
    const float* __restrict__ bias, float* __restrict__ C1, float* __restrict__ C2,
    int n1blk, int N, int K) {
    extern __shared__ __align__(1024) char smem[];
    const uint32_t sb = smem_u32(smem);
    const int tid = threadIdx.x, lane = tid & 31, w = tid >> 5;
    const int m0 = blockIdx.y * 128;
    const bool second = ((int)blockIdx.x >= n1blk);
    const int n0 = (second ? (int)blockIdx.x - n1blk : (int)blockIdx.x) * 128;
    const ushort_t* Wh = second ? W2 : W1;
    float* C = second ? C2 : C1;
    const int wm = (w & 3) * 32, wn = (w >> 2) * 64;
    const int NC = K >> 6;

    float acc[2][8][4];
#pragma unroll
    for (int i = 0; i < 2; i++)
#pragma unroll
        for (int j = 0; j < 8; j++)
#pragma unroll
            for (int q = 0; q < 4; q++) acc[i][j][q] = 0.0f;

    stage_load(Ah, Wh, sb + 0 * STAGE_B, m0, n0, 0, K, tid);  CP_COMMIT();
    stage_load(Ah, Wh, sb + 1 * STAGE_B, m0, n0, 64, K, tid); CP_COMMIT();

    for (int c = 0; c < NC; c++) {
        if (c + 1 < NC) { CP_WAIT1(); } else { CP_WAIT0(); }
        __syncthreads();
        const uint32_t stage = sb + (c & 1) * STAGE_B;
        stage_compute(stage, wm, wn, lane, acc);
        __syncthreads();
        if (c + 2 < NC) {
            stage_load(Ah, Wh, stage, m0, n0, (c + 2) * 64, K, tid);
            CP_COMMIT();
        }
    }

    // epilogue
    const int gm = m0 + wm, gn = n0 + wn;
    const int r = lane >> 2, cp = (lane & 3) * 2;
#pragma unroll
    for (int mi = 0; mi < 2; mi++) {
#pragma unroll
        for (int nj = 0; nj < 8; nj++) {
            int row = gm + mi * 16 + r;
            int col = gn + nj * 8 + cp;
            float v0 = acc[mi][nj][0], v1 = acc[mi][nj][1];
            float v2 = acc[mi][nj][2], v3 = acc[mi][nj][3];
            if (second) {
                float2 bb = *reinterpret_cast<const float2*>(&bias[col]);
                v0 = dt_transform(v0, bb.x);
                v1 = dt_transform(v1, bb.y);
                v2 = dt_transform(v2, bb.x);
                v3 = dt_transform(v3, bb.y);
            }
            *reinterpret_cast<float2*>(&C[(size_t)row * N + col]) = make_float2(v0, v1);
            *reinterpret_cast<float2*>(&C[(size_t)(row + 8) * N + col]) = make_float2(v2, v3);
        }
    }
}

// ---------------- B/C projection + row normalization ----------------
__global__ __launch_bounds__(128) void bc_kernel(const float* __restrict__ X,
                                                 const float* __restrict__ WB,
                                                 const float* __restrict__ WC) {
    int warp = threadIdx.x >> 5;
    int lane = threadIdx.x & 31;
    int m = blockIdx.x * 4 + warp;
    const float* Wr = (lane < 16) ? (WB + (size_t)lane * CDMODEL)
                                  : (WC + (size_t)(lane - 16) * CDMODEL);
    const float* Xr = X + (size_t)m * CDMODEL;

    float4 av = make_float4(0.f, 0.f, 0.f, 0.f);
    for (int k = 0; k < CDMODEL; k += 4) {
        float4 xv = *reinterpret_cast<const float4*>(&Xr[k]);
        float4 wv = *reinterpret_cast<const float4*>(&Wr[k]);
        av.x = fmaf(xv.x, wv.x, av.x);
        av.y = fmaf(xv.y, wv.y, av.y);
        av.z = fmaf(xv.z, wv.z, av.z);
        av.w = fmaf(xv.w, wv.w, av.w);
    }
    float acc = (av.x + av.y) + (av.z + av.w);

    float ss = acc * acc;
#pragma unroll
    for (int off = 8; off >= 1; off >>= 1)
        ss += __shfl_xor_sync(0xffffffffu, ss, off);
    float scale = 1.0f / fmaxf(sqrtf(ss), 1.0f);
    float v = acc * scale;
    if (lane < 16) g_Bn[(size_t)m * 16 + lane] = v;
    else           g_Cn[(size_t)m * 16 + (lane - 16)] = v;
}

__device__ __forceinline__ void load16(const float* p, float* v) {
    const float4* q = reinterpret_cast<const float4*>(p);
    float4 a = q[0], b = q[1], c = q[2], d = q[3];
    v[0] = a.x; v[1] = a.y; v[2] = a.z; v[3] = a.w;
    v[4] = b.x; v[5] = b.y; v[6] = b.z; v[7] = b.w;
    v[8] = c.x; v[9] = c.y; v[10] = c.z; v[11] = c.w;
    v[12] = d.x; v[13] = d.y; v[14] = d.z; v[15] = d.w;
}

__device__ __forceinline__ bool load_A(const float* __restrict__ A_log, int d, float* Av) {
    int head = d / CHEADDIM;
    bool fast = true;
#pragma unroll
    for (int n = 0; n < 16; n++) {
        Av[n] = expf(A_log[head * 16 + n]);
        if (fabsf(Av[n] - (float)(n + 1)) > 1e-3f * (float)(n + 1)) fast = false;
    }
    return fast;
}

// ---------------- scan pass 1: 2 channels/thread (d and d+1024) ----------------
__global__ __launch_bounds__(256) void scan_pass1(const float* __restrict__ A_log) {
    int d0 = blockIdx.x * 256 + threadIdx.x;   // 0..1023
    int d1 = d0 + CHALF;
    int c = blockIdx.y;
    int b = blockIdx.z;

    float Av0[16], Av1[16];
    bool fastA = load_A(A_log, d0, Av0) && load_A(A_log, d1, Av1);

    float h0[16], h1[16];
#pragma unroll
    for (int n = 0; n < 16; n++) { h0[n] = 0.0f; h1[n] = 0.0f; }
    float S0 = 0.0f, S1 = 0.0f;

    int row0 = b * CSEQ + c * CLCHUNK;
    for (int t = 0; t < CLCHUNK; t++) {
        size_t ro = (size_t)(row0 + t) * CDMAMBA + d0;
        float dt0 = g_dt[ro],         x0 = g_xssm[ro];
        float dt1 = g_dt[ro + CHALF], x1 = g_xssm[ro + CHALF];
        float Bv[16];
        load16(g_Bn + (size_t)(row0 + t) * 16, Bv);
        S0 += dt0; S1 += dt1;
        float dtx0 = dt0 * x0, dtx1 = dt1 * x1;
        if (fastA) {
            float r0 = __expf(-dt0), p0 = 1.0f;
            float r1 = __expf(-dt1), p1 = 1.0f;
#pragma unroll
            for (int n = 0; n < 16; n++) {
                p0 *= r0; h0[n] = fmaf(p0, h0[n], dtx0 * Bv[n]);
                p1 *= r1; h1[n] = fmaf(p1, h1[n], dtx1 * Bv[n]);
            }
        } else {
#pragma unroll
            for (int n = 0; n < 16; n++) {
                h0[n] = fmaf(__expf(-dt0 * Av0[n]), h0[n], dtx0 * Bv[n]);
                h1[n] = fmaf(__expf(-dt1 * Av1[n]), h1[n], dtx1 * Bv[n]);
            }
        }
    }
    size_t base = ((size_t)(b * CNCHUNK + c) * 16) * CDMAMBA + d0;
#pragma unroll
    for (int n = 0; n < 16; n++) {
        g_hloc[base + (size_t)n * CDMAMBA] = h0[n];
        g_hloc[base + (size_t)n * CDMAMBA + CHALF] = h1[n];
    }
    g_S[(size_t)(b * CNCHUNK + c) * CDMAMBA + d0] = S0;
    g_S[(size_t)(b * CNCHUNK + c) * CDMAMBA + d1] = S1;
}

// ---------------- scan pass 2 ----------------
__global__ __launch_bounds__(256) void scan_pass2(const float* __restrict__ A_log) {
    int idx = blockIdx.x * 256 + threadIdx.x;
    int b = idx / CDMAMBA;
    int d = idx % CDMAMBA;

    float Av[16];
    bool fastA = load_A(A_log, d, Av);

    float h[16];
#pragma unroll
    for (int n = 0; n < 16; n++) h[n] = 0.0f;

    for (int c = 0; c < CNCHUNK; c++) {
        size_t base = ((size_t)(b * CNCHUNK + c) * 16) * CDMAMBA + d;
#pragma unroll
        for (int n = 0; n < 16; n++) g_hinit[base + (size_t)n * CDMAMBA] = h[n];
        float S = g_S[(size_t)(b * CNCHUNK + c) * CDMAMBA + d];
        if (fastA) {
            float R = __expf(-S), p = 1.0f;
#pragma unroll
            for (int n = 0; n < 16; n++) {
                p *= R;
                h[n] = fmaf(p, h[n], g_hloc[base + (size_t)n * CDMAMBA]);
            }
        } else {
#pragma unroll
            for (int n = 0; n < 16; n++) {
                float P = __expf(-S * Av[n]);
                h[n] = fmaf(P, h[n], g_hloc[base + (size_t)n * CDMAMBA]);
            }
        }
    }
}

// ---------------- scan pass 3: 2 channels/thread, emit y as fp16 ----------------
__global__ __launch_bounds__(256) void scan_pass3(const float* __restrict__ A_log,
                                                  const float* __restrict__ Dvec) {
    int d0 = blockIdx.x * 256 + threadIdx.x;   // 0..1023
    int d1 = d0 + CHALF;
    int c = blockIdx.y;
    int b = blockIdx.z;

    float Av0[16], Av1[16];
    bool fastA = load_A(A_log, d0, Av0) && load_A(A_log, d1, Av1);
    float Dd0 = Dvec[d0], Dd1 = Dvec[d1];

    float h0[16], h1[16];
    size_t base = ((size_t)(b * CNCHUNK + c) * 16) * CDMAMBA + d0;
#pragma unroll
    for (int n = 0; n < 16; n++) {
        h0[n] = g_hinit[base + (size_t)n * CDMAMBA];
        h1[n] = g_hinit[base + (size_t)n * CDMAMBA + CHALF];
    }

    int row0 = b * CSEQ + c * CLCHUNK;
    for (int t = 0; t < CLCHUNK; t++) {
        size_t ro = (size_t)(row0 + t) * CDMAMBA + d0;
        float dt0 = g_dt[ro],         x0 = g_xssm[ro];
        float dt1 = g_dt[ro + CHALF], x1 = g_xssm[ro + CHALF];
        float Bv[16], Cv[16];
        load16(g_Bn + (size_t)(row0 + t) * 16, Bv);
        load16(g_Cn + (size_t)(row0 + t) * 16, Cv);
        float dtx0 = dt0 * x0, dtx1 = dt1 * x1;
        float y0 = 0.0f, y1 = 0.0f;
        if (fastA) {
            float r0 = __expf(-dt0), p0 = 1.0f;
            float r1 = __expf(-dt1), p1 = 1.0f;
#pragma unroll
            for (int n = 0; n < 16; n++) {
                p0 *= r0; h0[n] = fmaf(p0, h0[n], dtx0 * Bv[n]); y0 = fmaf(h0[n], Cv[n], y0);
                p1 *= r1; h1[n] = fmaf(p1, h1[n], dtx1 * Bv[n]); y1 = fmaf(h1[n], Cv[n], y1);
            }
        } else {
#pragma unroll
            for (int n = 0; n < 16; n++) {
                h0[n] = fmaf(__expf(-dt0 * Av0[n]), h0[n], dtx0 * Bv[n]); y0 = fmaf(h0[n], Cv[n], y0);
                h1[n] = fmaf(__expf(-dt1 * Av1[n]), h1[n], dtx1 * Bv[n]); y1 = fmaf(h1[n], Cv[n], y1);
            }
        }
        g_y_h[ro]         = __half_as_ushort(__float2half(fmaf(x0, Dd0, y0)));
        g_y_h[ro + CHALF] = __half_as_ushort(__float2half(fmaf(x1, Dd1, y1)));
    }
}

// ---------------- launch ----------------
extern "C" void kernel_launch(void* const* d_in, const int* in_sizes, int n_in,
                              void* d_out, int out_size) {
    (void)in_sizes; (void)n_in; (void)out_size;
    const float* x_norm     = (const float*)d_in[0];
    const float* x_proj_w   = (const float*)d_in[1];
    const float* dt_proj_w  = (const float*)d_in[2];
    const float* dt_proj_b  = (const float*)d_in[3];
    const float* B_proj_w   = (const float*)d_in[4];
    const float* C_proj_w   = (const float*)d_in[5];
    const float* A_log      = (const float*)d_in[6];
    const float* Dvec       = (const float*)d_in[7];
    const float* out_proj_w = (const float*)d_in[8];
    float* out = (float*)d_out;

    void *p_xssm, *p_dt;
    void *p_xnh, *p_w1h, *p_w2h, *p_w3h, *p_yh;
    cudaGetSymbolAddress(&p_xssm, g_xssm);
    cudaGetSymbolAddress(&p_dt, g_dt);
    cudaGetSymbolAddress(&p_xnh, g_xn_h);
    cudaGetSymbolAddress(&p_w1h, g_w1_h);
    cudaGetSymbolAddress(&p_w2h, g_w2_h);
    cudaGetSymbolAddress(&p_w3h, g_w3_h);
    cudaGetSymbolAddress(&p_yh, g_y_h);

    cudaFuncSetAttribute(gemm_mma, cudaFuncAttributeMaxDynamicSharedMemorySize, SM_TOTAL);

    // fp16 conversions
    {
        int n4 = (CMROWS * CDMODEL) / 4;
        conv_h<<<n4 / 256, 256>>>(x_norm, (ushort_t*)p_xnh, n4);
        n4 = (CDMAMBA * CDMODEL) / 4;
        conv_h<<<n4 / 256, 256>>>(x_proj_w, (ushort_t*)p_w1h, n4);
        conv_h<<<n4 / 256, 256>>>(dt_proj_w, (ushort_t*)p_w2h, n4);
        n4 = (CDMAMBA * CDMAMBA) / 4;
        conv_h<<<n4 / 256, 256>>>(out_proj_w, (ushort_t*)p_w3h, n4);
    }

    // 1+2) fused: x_ssm = x_norm @ W1^T ; dt = dt_transform(x_norm @ W2^T + b)
    {
        dim3 grid(2 * (CDMAMBA / 128), CMROWS / 128);   // (32, 64)
        gemm_mma<<<grid, 256, SM_TOTAL>>>(
            (const ushort_t*)p_xnh,
            (const ushort_t*)p_w1h, (const ushort_t*)p_w2h, dt_proj_b,
            (float*)p_xssm, (float*)p_dt,
            CDMAMBA / 128, CDMAMBA, CDMODEL);
    }
    // 3) normalized B, C
    bc_kernel<<<CMROWS / 4, 128>>>(x_norm, B_proj_w, C_proj_w);
    // 4-6) chunked selective scan (2 channels per thread in pass1/pass3)
    dim3 scan_grid(CHALF / 256, CNCHUNK, CBATCH);   // (4, 32, 4)
    scan_pass1<<<scan_grid, 256>>>(A_log);
    scan_pass2<<<(CBATCH * CDMAMBA) / 256, 256>>>(A_log);
    scan_pass3<<<scan_grid, 256>>>(A_log, Dvec);
    // 7) out = y @ out_proj_w^T
    {
        dim3 grid(CDMAMBA / 128, CMROWS / 128);   // (16, 64)
        gemm_mma<<<grid, 256, SM_TOTAL>>>(
            (const ushort_t*)p_yh,
            (const ushort_t*)p_w3h, (const ushort_t*)p_w3h, nullptr,
            out, out,
            CDMAMBA / 128, CDMAMBA, CDMAMBA);
    }
}

// round 8
// speedup vs baseline: 2.2274x; 1.0558x over previous
#include <cuda_runtime.h>
#include <cuda_fp16.h>
#include <math.h>
#include <stdint.h>

#define CBATCH   4
#define CSEQ     2048
#define CDMODEL  1024
#define CDMAMBA  2048
#define CDSTATE  16
#define CNHEADS  32
#define CMROWS   (CBATCH * CSEQ)          // 8192
#define CNCHUNK  32
#define CLCHUNK  (CSEQ / CNCHUNK)         // 64
#define CHEADDIM (CDMAMBA / CNHEADS)      // 64
#define CHALF    (CDMAMBA / 2)            // 1024

typedef unsigned short ushort_t;

// ---------------- scratch (static device arrays; no runtime allocation) ----------------
__device__ float g_Bn  [CMROWS * CDSTATE];
__device__ float g_Cn  [CMROWS * CDSTATE];
__device__ float g_hloc [CBATCH * CNCHUNK * CDSTATE * CDMAMBA];
__device__ float g_hinit[CBATCH * CNCHUNK * CDSTATE * CDMAMBA];
__device__ float g_S    [CBATCH * CNCHUNK * CDMAMBA];

// fp16 operands / intermediates
__device__ ushort_t g_xn_h[CMROWS * CDMODEL];
__device__ ushort_t g_w1_h[CDMAMBA * CDMODEL];
__device__ ushort_t g_w2_h[CDMAMBA * CDMODEL];
__device__ ushort_t g_w3_h[CDMAMBA * CDMAMBA];
__device__ ushort_t g_x16 [CMROWS * CDMAMBA];   // x_ssm fp16
__device__ ushort_t g_dt16[CMROWS * CDMAMBA];   // dt fp16
__device__ ushort_t g_y_h [CMROWS * CDMAMBA];   // y fp16

// ---------------- PTX helpers (baseline sm_80-level features only) ----------------
__device__ __forceinline__ uint32_t smem_u32(const void* p) {
    uint32_t a;
    asm("{ .reg .u64 t; cvta.to.shared.u64 t, %1; cvt.u32.u64 %0, t; }" : "=r"(a) : "l"(p));
    return a;
}

#define CP_ASYNC16(dst, src) \
    asm volatile("cp.async.cg.shared.global [%0], [%1], 16;" :: "r"(dst), "l"(src))
#define CP_COMMIT() asm volatile("cp.async.commit_group;" ::: "memory")
#define CP_WAIT0() asm volatile("cp.async.wait_group 0;" ::: "memory")
#define CP_WAIT1() asm volatile("cp.async.wait_group 1;" ::: "memory")

#define LDSM4(r, addr) \
    asm volatile("ldmatrix.sync.aligned.m8n8.x4.shared.b16 {%0,%1,%2,%3}, [%4];" \
        : "=r"((r)[0]), "=r"((r)[1]), "=r"((r)[2]), "=r"((r)[3]) : "r"(addr))

#define MMA_F16(d, a, b0, b1) \
    asm volatile("mma.sync.aligned.m16n8k16.row.col.f32.f16.f16.f32 " \
        "{%0,%1,%2,%3}, {%4,%5,%6,%7}, {%8,%9}, {%0,%1,%2,%3};" \
        : "+f"((d)[0]), "+f"((d)[1]), "+f"((d)[2]), "+f"((d)[3]) \
        : "r"((a)[0]), "r"((a)[1]), "r"((a)[2]), "r"((a)[3]), "r"(b0), "r"(b1))

__device__ __forceinline__ uint32_t swz(uint32_t off) {   // SW128 xor swizzle
    return off ^ ((off >> 3) & 0x70);
}

// ---------------- fp16 conversion ----------------
__global__ __launch_bounds__(256) void conv_h(const float* __restrict__ in,
                                              ushort_t* __restrict__ hi, int n4) {
    int i = blockIdx.x * 256 + threadIdx.x;
    if (i >= n4) return;
    float4 v = reinterpret_cast<const float4*>(in)[i];
    ushort4 h;
    h.x = __half_as_ushort(__float2half(v.x));
    h.y = __half_as_ushort(__float2half(v.y));
    h.z = __half_as_ushort(__float2half(v.z));
    h.w = __half_as_ushort(__float2half(v.w));
    reinterpret_cast<ushort4*>(hi)[i] = h;
}

__device__ __forceinline__ float dt_transform(float v, float b) {
    v += b;
    v = fminf(fmaxf(v, -10.0f), 5.0f);
    v = log1pf(expf(v));
    return fminf(fmaxf(v, 1e-4f), 0.1f);
}

// ---------------- HMMA fp16 GEMM: 3-stage single-sync pipeline, R4 geometry ----------------
// C[m,n] = sum_k A[m,k]*W[n,k]; tile 128x128, BK=64, 8 warps (4x2), 32x64 warp tiles.
// 3 stages x 32KB = 96KB/CTA, 2 CTA/SM, one __syncthreads per K-chunk.
#define TILE_B   16384
#define STAGE_B  32768
#define SM_TOTAL (3 * STAGE_B)   // 98304

__device__ __forceinline__ void stage_load(
    const ushort_t* __restrict__ Ah, const ushort_t* __restrict__ Wh,
    uint32_t sbase, int m0, int n0, int kc, int K, int tid) {
#pragma unroll
    for (int tile = 0; tile < 2; tile++) {
        const ushort_t* g = (tile == 0) ? Ah : Wh;
        int row0 = (tile == 0) ? m0 : n0;
#pragma unroll
        for (int j = 0; j < 4; j++) {
            int idx = tid + j * 256;           // 0..1023
            int row = idx >> 3, seg = idx & 7;
            const ushort_t* src = g + (size_t)(row0 + row) * K + kc + seg * 8;
            uint32_t dst = sbase + tile * TILE_B + swz((uint32_t)(row * 128 + seg * 16));
            CP_ASYNC16(dst, src);
        }
    }
}

__device__ __forceinline__ void stage_compute(uint32_t sbase, int wm, int wn,
                                              int lane, float acc[2][8][4]) {
    const uint32_t aAh = sbase;
    const uint32_t aWh = sbase + TILE_B;
    const int arow = wm + (lane & 15);
    const int akb  = (lane >> 4) * 16;
    const int brow = wn + ((lane >> 4) << 3) + (lane & 7);
    const int bkb  = ((lane >> 3) & 1) * 16;

#pragma unroll
    for (int ks = 0; ks < 4; ks++) {
        const int kb = ks * 32;
        uint32_t ah[2][4];
#pragma unroll
        for (int mi = 0; mi < 2; mi++) {
            uint32_t off = swz((uint32_t)((arow + mi * 16) * 128 + akb + kb));
            LDSM4(ah[mi], aAh + off);
        }
        uint32_t bh[4][4];
#pragma unroll
        for (int ni = 0; ni < 4; ni++) {
            uint32_t off = swz((uint32_t)((brow + ni * 16) * 128 + bkb + kb));
            LDSM4(bh[ni], aWh + off);
        }
#pragma unroll
        for (int mi = 0; mi < 2; mi++) {
#pragma unroll
            for (int ni = 0; ni < 4; ni++) {
                MMA_F16(acc[mi][2 * ni + 0], ah[mi], bh[ni][0], bh[ni][1]);
                MMA_F16(acc[mi][2 * ni + 1], ah[mi], bh[ni][2], bh[ni][3]);
            }
        }
    }
}

// OUT16=true : blocks < n1blk write C1h = fp16(A*W1^T); blocks >= n1blk write
//              C2h = fp16(dt_transform(A*W2^T + bias)).
// OUT16=false: all blocks write Cf (fp32) = A*W1^T.
template <bool OUT16>
__global__ __launch_bounds__(256, 2) void gemm_mma(
    const ushort_t* __restrict__ Ah,
    const ushort_t* __restrict__ W1, const ushort_t* __restrict__ W2,
    const float* __restrict__ bias,
    ushort_t* __restrict__ C1h, ushort_t* __restrict__ C2h, float* __restrict__ Cf,
    int n1blk, int N, int K) {
    extern __shared__ __align__(1024) char smem[];
    const uint32_t sb = smem_u32(smem);
    const int tid = threadIdx.x, lane = tid & 31, w = tid >> 5;
    const int m0 = blockIdx.y * 128;
    const bool second = ((int)blockIdx.x >= n1blk);
    const int n0 = (second ? (int)blockIdx.x - n1blk : (int)blockIdx.x) * 128;
    const ushort_t* Wh = second ? W2 : W1;
    const int wm = (w & 3) * 32, wn = (w >> 2) * 64;
    const int NC = K >> 6;

    float acc[2][8][4];
#pragma unroll
    for (int i = 0; i < 2; i++)
#pragma unroll
        for (int j = 0; j < 8; j++)
#pragma unroll
            for (int q = 0; q < 4; q++) acc[i][j][q] = 0.0f;

    stage_load(Ah, Wh, sb + 0 * STAGE_B, m0, n0, 0, K, tid);  CP_COMMIT();
    stage_load(Ah, Wh, sb + 1 * STAGE_B, m0, n0, 64, K, tid); CP_COMMIT();

    int sc = 0, sl = 2;
    for (int c = 0; c < NC; c++) {
        if (c + 1 < NC) { CP_WAIT1(); } else { CP_WAIT0(); }
        __syncthreads();
        // load buffer sl == buffer consumed at iter c-1; all warps are past it (sync above)
        if (c + 2 < NC) {
            stage_load(Ah, Wh, sb + sl * STAGE_B, m0, n0, (c + 2) * 64, K, tid);
            CP_COMMIT();
            sl = (sl == 2) ? 0 : sl + 1;
        }
        stage_compute(sb + sc * STAGE_B, wm, wn, lane, acc);
        sc = (sc == 2) ? 0 : sc + 1;
    }

    // epilogue
    const int gm = m0 + wm, gn = n0 + wn;
    const int r = lane >> 2, cp = (lane & 3) * 2;
#pragma unroll
    for (int mi = 0; mi < 2; mi++) {
#pragma unroll
        for (int nj = 0; nj < 8; nj++) {
            int row = gm + mi * 16 + r;
            int col = gn + nj * 8 + cp;
            float v0 = acc[mi][nj][0], v1 = acc[mi][nj][1];
            float v2 = acc[mi][nj][2], v3 = acc[mi][nj][3];
            if (OUT16) {
                if (second) {
                    float2 bb = *reinterpret_cast<const float2*>(&bias[col]);
                    v0 = dt_transform(v0, bb.x);
                    v1 = dt_transform(v1, bb.y);
                    v2 = dt_transform(v2, bb.x);
                    v3 = dt_transform(v3, bb.y);
                }
                ushort_t* C = second ? C2h : C1h;
                __half2 h01 = __halves2half2(__float2half(v0), __float2half(v1));
                __half2 h23 = __halves2half2(__float2half(v2), __float2half(v3));
                *reinterpret_cast<__half2*>(&C[(size_t)row * N + col]) = h01;
                *reinterpret_cast<__half2*>(&C[(size_t)(row + 8) * N + col]) = h23;
            } else {
                *reinterpret_cast<float2*>(&Cf[(size_t)row * N + col]) = make_float2(v0, v1);
                *reinterpret_cast<float2*>(&Cf[(size_t)(row + 8) * N + col]) = make_float2(v2, v3);
            }
        }
    }
}

// ---------------- B/C projection + row normalization ----------------
__global__ __launch_bounds__(128) void bc_kernel(const float* __restrict__ X,
                                                 const float* __restrict__ WB,
                                                 const float* __restrict__ WC) {
    int warp = threadIdx.x >> 5;
    int lane = threadIdx.x & 31;
    int m = blockIdx.x * 4 + warp;
    const float* Wr = (lane < 16) ? (WB + (size_t)lane * CDMODEL)
                                  : (WC + (size_t)(lane - 16) * CDMODEL);
    const float* Xr = X + (size_t)m * CDMODEL;

    float4 av = make_float4(0.f, 0.f, 0.f, 0.f);
    for (int k = 0; k < CDMODEL; k += 4) {
        float4 xv = *reinterpret_cast<const float4*>(&Xr[k]);
        float4 wv = *reinterpret_cast<const float4*>(&Wr[k]);
        av.x = fmaf(xv.x, wv.x, av.x);
        av.y = fmaf(xv.y, wv.y, av.y);
        av.z = fmaf(xv.z, wv.z, av.z);
        av.w = fmaf(xv.w, wv.w, av.w);
    }
    float acc = (av.x + av.y) + (av.z + av.w);

    float ss = acc * acc;
#pragma unroll
    for (int off = 8; off >= 1; off >>= 1)
        ss += __shfl_xor_sync(0xffffffffu, ss, off);
    float scale = 1.0f / fmaxf(sqrtf(ss), 1.0f);
    float v = acc * scale;
    if (lane < 16) g_Bn[(size_t)m * 16 + lane] = v;
    else           g_Cn[(size_t)m * 16 + (lane - 16)] = v;
}

__device__ __forceinline__ void load16(const float* p, float* v) {
    const float4* q = reinterpret_cast<const float4*>(p);
    float4 a = q[0], b = q[1], c = q[2], d = q[3];
    v[0] = a.x; v[1] = a.y; v[2] = a.z; v[3] = a.w;
    v[4] = b.x; v[5] = b.y; v[6] = b.z; v[7] = b.w;
    v[8] = c.x; v[9] = c.y; v[10] = c.z; v[11] = c.w;
    v[12] = d.x; v[13] = d.y; v[14] = d.z; v[15] = d.w;
}

__device__ __forceinline__ bool load_A(const float* __restrict__ A_log, int d, float* Av) {
    int head = d / CHEADDIM;
    bool fast = true;
#pragma unroll
    for (int n = 0; n < 16; n++) {
        Av[n] = expf(A_log[head * 16 + n]);
        if (fabsf(Av[n] - (float)(n + 1)) > 1e-3f * (float)(n + 1)) fast = false;
    }
    return fast;
}

__device__ __forceinline__ float ldh(const ushort_t* p) {
    return __half2float(__ushort_as_half(*p));
}

// ---------------- scan pass 1: 2 channels/thread (d and d+1024) ----------------
__global__ __launch_bounds__(256) void scan_pass1(const float* __restrict__ A_log) {
    int d0 = blockIdx.x * 256 + threadIdx.x;   // 0..1023
    int d1 = d0 + CHALF;
    int c = blockIdx.y;
    int b = blockIdx.z;

    float Av0[16], Av1[16];
    bool fastA = load_A(A_log, d0, Av0) && load_A(A_log, d1, Av1);

    float h0[16], h1[16];
#pragma unroll
    for (int n = 0; n < 16; n++) { h0[n] = 0.0f; h1[n] = 0.0f; }
    float S0 = 0.0f, S1 = 0.0f;

    int row0 = b * CSEQ + c * CLCHUNK;
    for (int t = 0; t < CLCHUNK; t++) {
        size_t ro = (size_t)(row0 + t) * CDMAMBA + d0;
        float dt0 = ldh(&g_dt16[ro]),         x0 = ldh(&g_x16[ro]);
        float dt1 = ldh(&g_dt16[ro + CHALF]), x1 = ldh(&g_x16[ro + CHALF]);
        float Bv[16];
        load16(g_Bn + (size_t)(row0 + t) * 16, Bv);
        S0 += dt0; S1 += dt1;
        float dtx0 = dt0 * x0, dtx1 = dt1 * x1;
        if (fastA) {
            float r0 = __expf(-dt0), p0 = 1.0f;
            float r1 = __expf(-dt1), p1 = 1.0f;
#pragma unroll
            for (int n = 0; n < 16; n++) {
                p0 *= r0; h0[n] = fmaf(p0, h0[n], dtx0 * Bv[n]);
                p1 *= r1; h1[n] = fmaf(p1, h1[n], dtx1 * Bv[n]);
            }
        } else {
#pragma unroll
            for (int n = 0; n < 16; n++) {
                h0[n] = fmaf(__expf(-dt0 * Av0[n]), h0[n], dtx0 * Bv[n]);
                h1[n] = fmaf(__expf(-dt1 * Av1[n]), h1[n], dtx1 * Bv[n]);
            }
        }
    }
    size_t base = ((size_t)(b * CNCHUNK + c) * 16) * CDMAMBA + d0;
#pragma unroll
    for (int n = 0; n < 16; n++) {
        g_hloc[base + (size_t)n * CDMAMBA] = h0[n];
        g_hloc[base + (size_t)n * CDMAMBA + CHALF] = h1[n];
    }
    g_S[(size_t)(b * CNCHUNK + c) * CDMAMBA + d0] = S0;
    g_S[(size_t)(b * CNCHUNK + c) * CDMAMBA + d1] = S1;
}

// ---------------- scan pass 2 ----------------
__global__ __launch_bounds__(256) void scan_pass2(const float* __restrict__ A_log) {
    int idx = blockIdx.x * 256 + threadIdx.x;
    int b = idx / CDMAMBA;
    int d = idx % CDMAMBA;

    float Av[16];
    bool fastA = load_A(A_log, d, Av);

    float h[16];
#pragma unroll
    for (int n = 0; n < 16; n++) h[n] = 0.0f;

    for (int c = 0; c < CNCHUNK; c++) {
        size_t base = ((size_t)(b * CNCHUNK + c) * 16) * CDMAMBA + d;
#pragma unroll
        for (int n = 0; n < 16; n++) g_hinit[base + (size_t)n * CDMAMBA] = h[n];
        float S = g_S[(size_t)(b * CNCHUNK + c) * CDMAMBA + d];
        if (fastA) {
            float R = __expf(-S), p = 1.0f;
#pragma unroll
            for (int n = 0; n < 16; n++) {
                p *= R;
                h[n] = fmaf(p, h[n], g_hloc[base + (size_t)n * CDMAMBA]);
            }
        } else {
#pragma unroll
            for (int n = 0; n < 16; n++) {
                float P = __expf(-S * Av[n]);
                h[n] = fmaf(P, h[n], g_hloc[base + (size_t)n * CDMAMBA]);
            }
        }
    }
}

// ---------------- scan pass 3: 2 channels/thread, emit y as fp16 ----------------
__global__ __launch_bounds__(256) void scan_pass3(const float* __restrict__ A_log,
                                                  const float* __restrict__ Dvec) {
    int d0 = blockIdx.x * 256 + threadIdx.x;   // 0..1023
    int d1 = d0 + CHALF;
    int c = blockIdx.y;
    int b = blockIdx.z;

    float Av0[16], Av1[16];
    bool fastA = load_A(A_log, d0, Av0) && load_A(A_log, d1, Av1);
    float Dd0 = Dvec[d0], Dd1 = Dvec[d1];

    float h0[16], h1[16];
    size_t base = ((size_t)(b * CNCHUNK + c) * 16) * CDMAMBA + d0;
#pragma unroll
    for (int n = 0; n < 16; n++) {
        h0[n] = g_hinit[base + (size_t)n * CDMAMBA];
        h1[n] = g_hinit[base + (size_t)n * CDMAMBA + CHALF];
    }

    int row0 = b * CSEQ + c * CLCHUNK;
    for (int t = 0; t < CLCHUNK; t++) {
        size_t ro = (size_t)(row0 + t) * CDMAMBA + d0;
        float dt0 = ldh(&g_dt16[ro]),         x0 = ldh(&g_x16[ro]);
        float dt1 = ldh(&g_dt16[ro + CHALF]), x1 = ldh(&g_x16[ro + CHALF]);
        float Bv[16], Cv[16];
        load16(g_Bn + (size_t)(row0 + t) * 16, Bv);
        load16(g_Cn + (size_t)(row0 + t) * 16, Cv);
        float dtx0 = dt0 * x0, dtx1 = dt1 * x1;
        float y0 = 0.0f, y1 = 0.0f;
        if (fastA) {
            float r0 = __expf(-dt0), p0 = 1.0f;
            float r1 = __expf(-dt1), p1 = 1.0f;
#pragma unroll
            for (int n = 0; n < 16; n++) {
                p0 *= r0; h0[n] = fmaf(p0, h0[n], dtx0 * Bv[n]); y0 = fmaf(h0[n], Cv[n], y0);
                p1 *= r1; h1[n] = fmaf(p1, h1[n], dtx1 * Bv[n]); y1 = fmaf(h1[n], Cv[n], y1);
            }
        } else {
#pragma unroll
            for (int n = 0; n < 16; n++) {
                h0[n] = fmaf(__expf(-dt0 * Av0[n]), h0[n], dtx0 * Bv[n]); y0 = fmaf(h0[n], Cv[n], y0);
                h1[n] = fmaf(__expf(-dt1 * Av1[n]), h1[n], dtx1 * Bv[n]); y1 = fmaf(h1[n], Cv[n], y1);
            }
        }
        g_y_h[ro]         = __half_as_ushort(__float2half(fmaf(x0, Dd0, y0)));
        g_y_h[ro + CHALF] = __half_as_ushort(__float2half(fmaf(x1, Dd1, y1)));
    }
}

// ---------------- launch ----------------
extern "C" void kernel_launch(void* const* d_in, const int* in_sizes, int n_in,
                              void* d_out, int out_size) {
    (void)in_sizes; (void)n_in; (void)out_size;
    const float* x_norm     = (const float*)d_in[0];
    const float* x_proj_w   = (const float*)d_in[1];
    const float* dt_proj_w  = (const float*)d_in[2];
    const float* dt_proj_b  = (const float*)d_in[3];
    const float* B_proj_w   = (const float*)d_in[4];
    const float* C_proj_w   = (const float*)d_in[5];
    const float* A_log      = (const float*)d_in[6];
    const float* Dvec       = (const float*)d_in[7];
    const float* out_proj_w = (const float*)d_in[8];
    float* out = (float*)d_out;

    void *p_xnh, *p_w1h, *p_w2h, *p_w3h, *p_yh, *p_x16, *p_dt16;
    cudaGetSymbolAddress(&p_xnh, g_xn_h);
    cudaGetSymbolAddress(&p_w1h, g_w1_h);
    cudaGetSymbolAddress(&p_w2h, g_w2_h);
    cudaGetSymbolAddress(&p_w3h, g_w3_h);
    cudaGetSymbolAddress(&p_yh, g_y_h);
    cudaGetSymbolAddress(&p_x16, g_x16);
    cudaGetSymbolAddress(&p_dt16, g_dt16);

    cudaFuncSetAttribute(gemm_mma<true>, cudaFuncAttributeMaxDynamicSharedMemorySize, SM_TOTAL);
    cudaFuncSetAttribute(gemm_mma<false>, cudaFuncAttributeMaxDynamicSharedMemorySize, SM_TOTAL);

    // fp16 conversions
    {
        int n4 = (CMROWS * CDMODEL) / 4;
        conv_h<<<n4 / 256, 256>>>(x_norm, (ushort_t*)p_xnh, n4);
        n4 = (CDMAMBA * CDMODEL) / 4;
        conv_h<<<n4 / 256, 256>>>(x_proj_w, (ushort_t*)p_w1h, n4);
        conv_h<<<n4 / 256, 256>>>(dt_proj_w, (ushort_t*)p_w2h, n4);
        n4 = (CDMAMBA * CDMAMBA) / 4;
        conv_h<<<n4 / 256, 256>>>(out_proj_w, (ushort_t*)p_w3h, n4);
    }

    // 1+2) fused: x16 = fp16(x_norm @ W1^T) ; dt16 = fp16(dt_transform(x_norm @ W2^T + b))
    {
        dim3 grid(2 * (CDMAMBA / 128), CMROWS / 128);   // (32, 64)
        gemm_mma<true><<<grid, 256, SM_TOTAL>>>(
            (const ushort_t*)p_xnh,
            (const ushort_t*)p_w1h, (const ushort_t*)p_w2h, dt_proj_b,
            (ushort_t*)p_x16, (ushort_t*)p_dt16, nullptr,
            CDMAMBA / 128, CDMAMBA, CDMODEL);
    }
    // 3) normalized B, C
    bc_kernel<<<CMROWS / 4, 128>>>(x_norm, B_proj_w, C_proj_w);
    // 4-6) chunked selective scan (2 channels per thread in pass1/pass3)
    dim3 scan_grid(CHALF / 256, CNCHUNK, CBATCH);   // (4, 32, 4)
    scan_pass1<<<scan_grid, 256>>>(A_log);
    scan_pass2<<<(CBATCH * CDMAMBA) / 256, 256>>>(A_log);
    scan_pass3<<<scan_grid, 256>>>(A_log, Dvec);
    // 7) out = y @ out_proj_w^T  (fp32 output)
    {
        dim3 grid(CDMAMBA / 128, CMROWS / 128);   // (16, 64)
        gemm_mma<false><<<grid, 256, SM_TOTAL>>>(
            (const ushort_t*)p_yh,
            (const ushort_t*)p_w3h, (const ushort_t*)p_w3h, nullptr,
            nullptr, nullptr, out,
            CDMAMBA / 128, CDMAMBA, CDMAMBA);
    }
}